// round 4
// baseline (speedup 1.0000x reference)
#include <cuda_runtime.h>
#include <stdint.h>

// SGC 2-hop: out = S^2 x W^T + b,  S = D^-1/2 (A + I) D^-1/2
// Identity: (S^2 x) W^T == S^2 (x W^T) -> project features to scalar FIRST,
// then two scalar scatter passes over edges.
//
// With z = dis * y (dis = deg^-1/2):
//   s[c]  = z[c] + sum_{edges r->c} z[r]   (self-loop folded into init)
//   z'[c] = dis[c]^2 * s[c]
//   out[c] = dis[c] * s2[c] + b

#define MAXN  100000
#define DFEAT 128

__device__ int   g_cnt[MAXN];   // in-degree (excl. self loop)
__device__ float g_dis[MAXN];   // deg^-1/2
__device__ float g_z[MAXN];     // scalar being propagated
__device__ float g_acc[MAXN];   // scatter accumulator
__device__ int   g_is32;        // 1 if edge_index buffer is int32

// ---- index fetch helper: handles int32 or int64 layout ----
__device__ __forceinline__ int load_idx(const void* ei, int is32, long long pos) {
    if (is32) return ((const int*)ei)[pos];
    return (int)((const long long*)ei)[pos];
}

// ---- kernel 0: zero counts + reset flag ----
__global__ void k_init(int n) {
    int i = blockIdx.x * blockDim.x + threadIdx.x;
    if (i == 0) g_is32 = 0;
    if (i < n) g_cnt[i] = 0;
}

// ---- kernel 1: detect index dtype.
// int64 little-endian values < 2^31  => every odd 32-bit word is 0.
// genuine int32 random indices       => many odd words nonzero.
__global__ void k_detect(const int* __restrict__ w, int e) {
    int i = blockIdx.x * blockDim.x + threadIdx.x;
    if (i < e && w[2 * i + 1] != 0) g_is32 = 1;  // racy same-value store: fine
}

// ---- kernel 2: count in-degree over col ----
__global__ void k_count(const void* __restrict__ ei, int e, int n) {
    int i = blockIdx.x * blockDim.x + threadIdx.x;
    if (i >= e) return;
    int c = load_idx(ei, g_is32, (long long)e + i);
    if ((unsigned)c < (unsigned)n) atomicAdd(&g_cnt[c], 1);
}

// ---- kernel 3: y = x @ W^T (warp/row); z = dis*y; acc = z (self loop) ----
__global__ void k_project(const float* __restrict__ x,
                          const float* __restrict__ W, int n) {
    int warp = (blockIdx.x * blockDim.x + threadIdx.x) >> 5;
    int lane = threadIdx.x & 31;
    if (warp >= n) return;
    const float4* xv = reinterpret_cast<const float4*>(x) + (size_t)warp * (DFEAT / 4);
    const float4* wv = reinterpret_cast<const float4*>(W);
    float4 a = xv[lane];
    float4 w = wv[lane];
    float d = a.x * w.x + a.y * w.y + a.z * w.z + a.w * w.w;
    #pragma unroll
    for (int off = 16; off > 0; off >>= 1)
        d += __shfl_down_sync(0xFFFFFFFFu, d, off);
    if (lane == 0) {
        float dis = rsqrtf((float)(g_cnt[warp] + 1));  // +1 self loop => deg>=1
        float z = dis * d;
        g_dis[warp] = dis;
        g_z[warp]   = z;
        g_acc[warp] = z;
    }
}

// ---- kernel 4: acc[col] += z[row]  (returnless atomic -> REDG) ----
__global__ void k_scatter(const void* __restrict__ ei, int e, int n) {
    int i = blockIdx.x * blockDim.x + threadIdx.x;
    if (i >= e) return;
    int is32 = g_is32;
    int r = load_idx(ei, is32, i);
    int c = load_idx(ei, is32, (long long)e + i);
    if ((unsigned)r < (unsigned)n && (unsigned)c < (unsigned)n)
        atomicAdd(&g_acc[c], g_z[r]);
}

// ---- kernel 5: z' = dis^2 * acc; acc = z' (self loop for next hop) ----
__global__ void k_rescale(int n) {
    int i = blockIdx.x * blockDim.x + threadIdx.x;
    if (i < n) {
        float dis = g_dis[i];
        float v = dis * dis * g_acc[i];
        g_z[i]   = v;
        g_acc[i] = v;
    }
}

// ---- kernel 6: out = dis * acc + b ----
__global__ void k_finish(float* __restrict__ out,
                         const float* __restrict__ b, int n) {
    int i = blockIdx.x * blockDim.x + threadIdx.x;
    if (i < n) out[i] = g_dis[i] * g_acc[i] + b[0];
}

extern "C" void kernel_launch(void* const* d_in, const int* in_sizes, int n_in,
                              void* d_out, int out_size) {
    const float* x  = (const float*)d_in[0];
    const void*  ei = d_in[1];                 // [2, E], int32 or int64
    const float* W  = (const float*)d_in[2];
    const float* b  = (const float*)d_in[3];
    float* out = (float*)d_out;

    int n = in_sizes[0] / DFEAT;      // 100000
    int e = in_sizes[1] / 2;          // 600000

    const int T = 256;
    int gbN = (n + T - 1) / T;
    int gbE = (e + T - 1) / T;
    int gbW = (n * 32 + T - 1) / T;   // warp-per-row

    k_init   <<<gbN, T>>>(n);
    k_detect <<<gbE, T>>>((const int*)ei, e);
    k_count  <<<gbE, T>>>(ei, e, n);
    k_project<<<gbW, T>>>(x, W, n);
    k_scatter<<<gbE, T>>>(ei, e, n);   // hop 1
    k_rescale<<<gbN, T>>>(n);
    k_scatter<<<gbE, T>>>(ei, e, n);   // hop 2
    k_finish <<<gbN, T>>>(out, b, n);
}

// round 7
// speedup vs baseline: 1.1156x; 1.1156x over previous
#include <cuda_runtime.h>
#include <stdint.h>

// SGC 2-hop: out = S^2 x W^T + b,  S = D^-1/2 (A + I) D^-1/2
// Identity: (S^2 x) W^T == S^2 (x W^T) -> project features to scalar FIRST,
// then two scalar scatter passes over edges (L2-resident accumulators).

#define MAXN  100000
#define DFEAT 128
#define PROWS 8          // rows per warp in k_project

__device__ int   g_cnt[MAXN];   // in-degree (excl. self loop)
__device__ float g_dis[MAXN];   // deg^-1/2
__device__ float g_z[MAXN];     // scalar being propagated
__device__ float g_acc[MAXN];   // scatter accumulator
__device__ int   g_is32;        // zero-init at load; sticky: only ever set to 1

__device__ __forceinline__ int load_idx(const void* ei, int is32, long long pos) {
    if (is32) return __ldg((const int*)ei + pos);
    return (int)__ldg((const long long*)ei + pos);
}

// ---- kernel 0 (fused): zero counts + detect index dtype.
// int64 LE values < 2^31 => every odd 32-bit word in the row half is 0.
// Sticky flag: never reset, so graph replays are deterministic.
__global__ void k_init_detect(const int* __restrict__ w, int e, int n) {
    int i = blockIdx.x * blockDim.x + threadIdx.x;
    if (i < n) g_cnt[i] = 0;
    if (i < e && __ldg(w + 2 * i + 1) != 0) g_is32 = 1;
}

// ---- kernel 1: count in-degree over col ----
__global__ void k_count(const void* __restrict__ ei, int e, int n) {
    int i = blockIdx.x * blockDim.x + threadIdx.x;
    if (i >= e) return;
    int c = load_idx(ei, g_is32, (long long)e + i);
    if ((unsigned)c < (unsigned)n) atomicAdd(&g_cnt[c], 1);
}

// ---- kernel 2: y = x @ W^T, 8 rows per warp for MLP; z = dis*y; acc = z ----
__global__ void k_project(const float* __restrict__ x,
                          const float* __restrict__ W, int n) {
    int warp = (blockIdx.x * blockDim.x + threadIdx.x) >> 5;
    int lane = threadIdx.x & 31;
    int base = warp * PROWS;
    if (base >= n) return;

    int rows = n - base; if (rows > PROWS) rows = PROWS;

    float4 w = reinterpret_cast<const float4*>(W)[lane];
    const float4* xv = reinterpret_cast<const float4*>(x)
                       + (size_t)base * (DFEAT / 4) + lane;

    // batch-issue 8 independent loads (MLP=8, front-batched in SASS)
    float4 a[PROWS];
    #pragma unroll
    for (int j = 0; j < PROWS; j++)
        if (j < rows) a[j] = xv[(size_t)j * (DFEAT / 4)];

    #pragma unroll
    for (int j = 0; j < PROWS; j++) {
        if (j >= rows) break;
        float d = a[j].x * w.x + a[j].y * w.y + a[j].z * w.z + a[j].w * w.w;
        #pragma unroll
        for (int off = 16; off > 0; off >>= 1)
            d += __shfl_down_sync(0xFFFFFFFFu, d, off);
        if (lane == 0) {
            int node = base + j;
            float dis = rsqrtf((float)(g_cnt[node] + 1));  // +1 self loop
            float z = dis * d;
            g_dis[node] = dis;
            g_z[node]   = z;
            g_acc[node] = z;   // self-loop contribution
        }
    }
}

// ---- kernel 3: acc[col] += z[row]  (returnless atomic -> REDG, L2-resident) ----
__global__ void k_scatter(const void* __restrict__ ei, int e, int n) {
    int i = blockIdx.x * blockDim.x + threadIdx.x;
    if (i >= e) return;
    int is32 = g_is32;
    int r = load_idx(ei, is32, i);
    int c = load_idx(ei, is32, (long long)e + i);
    if ((unsigned)r < (unsigned)n && (unsigned)c < (unsigned)n)
        atomicAdd(&g_acc[c], __ldg(&g_z[r]));
}

// ---- kernel 4: z' = dis^2 * acc; acc = z' (self loop for next hop) ----
__global__ void k_rescale(int n) {
    int i = blockIdx.x * blockDim.x + threadIdx.x;
    if (i < n) {
        float dis = g_dis[i];
        float v = dis * dis * g_acc[i];
        g_z[i]   = v;
        g_acc[i] = v;
    }
}

// ---- kernel 5: out = dis * acc + b ----
__global__ void k_finish(float* __restrict__ out,
                         const float* __restrict__ b, int n) {
    int i = blockIdx.x * blockDim.x + threadIdx.x;
    if (i < n) out[i] = g_dis[i] * g_acc[i] + b[0];
}

extern "C" void kernel_launch(void* const* d_in, const int* in_sizes, int n_in,
                              void* d_out, int out_size) {
    const float* x  = (const float*)d_in[0];
    const void*  ei = d_in[1];                 // [2, E], int32 or int64
    const float* W  = (const float*)d_in[2];
    const float* b  = (const float*)d_in[3];
    float* out = (float*)d_out;

    int n = in_sizes[0] / DFEAT;      // 100000
    int e = in_sizes[1] / 2;          // 600000

    const int T = 256;
    int gbN = (n + T - 1) / T;
    int gbE = (e + T - 1) / T;
    int nwarps = (n + PROWS - 1) / PROWS;
    int gbP = (nwarps * 32 + T - 1) / T;

    k_init_detect<<<gbE, T>>>((const int*)ei, e, n);
    k_count      <<<gbE, T>>>(ei, e, n);
    k_project    <<<gbP, T>>>(x, W, n);
    k_scatter    <<<gbE, T>>>(ei, e, n);   // hop 1
    k_rescale    <<<gbN, T>>>(n);
    k_scatter    <<<gbE, T>>>(ei, e, n);   // hop 2
    k_finish     <<<gbN, T>>>(out, b, n);
}